// round 2
// baseline (speedup 1.0000x reference)
#include <cuda_runtime.h>
#include <math.h>

// Problem constants
#define Cc    192
#define NHh   6
#define HDd   32
#define Tt    64      // tokens per window (8x8)
#define NWIN  4096    // 4 * 32 * 32 windows
#define SHIFTc 4

// SMEM layout (floats)
#define LDX 65        // padded stride for XsT / OsT / Res
#define LDQ 65        // padded stride for Qt / Kt
#define OFF_X 0
#define OFF_Q 12480   // 192*65
#define OFF_K 24960
#define OFF_V 37440   // Vs [64][192] = 12288
#define OFF_W 49728   // Wt chunk 32*192=6144  (also S buffer 64*64=4096)
#define SMEM_FLOATS 55872
#define SMEM_BYTES  (SMEM_FLOATS * 4)  // 223488

__global__ void __launch_bounds__(256, 1)
swin_fused_kernel(const float* __restrict__ x,
                  const float* __restrict__ qkv_w,
                  const float* __restrict__ qkv_b,
                  const float* __restrict__ proj_w,
                  const float* __restrict__ proj_b,
                  float* __restrict__ out)
{
    extern __shared__ float smem[];
    float* XsT = smem + OFF_X;   // [192][LDX]  A^T for QKV GEMM; later OsT
    float* Qt  = smem + OFF_Q;   // [192][LDQ]  Q^T (j = h*32+d, cols tokens); later Res
    float* Kt  = smem + OFF_K;   // [192][LDQ]  K^T
    float* Vs  = smem + OFF_V;   // [64][192]   V token-major
    float* Wt  = smem + OFF_W;   // [32][192]   weight chunk; also S [64][64]
    float* S   = Wt;

    const int tid = threadIdx.x;
    const int wid = blockIdx.x;
    const int b  = wid >> 10;
    const int wy = (wid >> 5) & 31;
    const int wx = wid & 31;

    const int ty = tid >> 4;   // 0..15 -> rows ty*4 + i
    const int tx = tid & 15;   // 0..15 -> cols tx*12 + jj (GEMM) / tx*4+j (S) / tx*2+jj (O)

    const int baseH = wy * 8 + SHIFTc;
    const int baseW = wx * 8 + SHIFTc;

    // ---- Gather window input (with roll) into XsT [c][t], coalesced ----
    {
        const float* xb = x + (size_t)b * Cc * 65536;
        for (int idx = tid; idx < Cc * Tt; idx += 256) {
            int c = idx >> 6, t = idx & 63;
            int ih = (baseH + (t >> 3)) & 255;
            int iw = (baseW + (t & 7)) & 255;
            XsT[c * LDX + t] = xb[c * 65536 + ih * 256 + iw];
        }
    }
    __syncthreads();

    // ---- QKV GEMM: 3 passes (q,k,v), each 64x192 out over K=192 ----
    #pragma unroll 1
    for (int p = 0; p < 3; ++p) {
        float acc[4][12];
        #pragma unroll
        for (int i = 0; i < 4; ++i)
            #pragma unroll
            for (int jj = 0; jj < 12; ++jj) acc[i][jj] = 0.0f;

        #pragma unroll 1
        for (int kc = 0; kc < 6; ++kc) {
            __syncthreads();  // previous Wt use done
            // load weight chunk: rows kc*32..+31, cols p*192..+191
            for (int v = tid; v < (32 * Cc) / 4; v += 256) {
                int row = v / 48, col4 = v % 48;
                ((float4*)Wt)[v] =
                    ((const float4*)(qkv_w + (size_t)(kc * 32 + row) * 576 + p * 192))[col4];
            }
            __syncthreads();

            #pragma unroll 4
            for (int kk = 0; kk < 32; ++kk) {
                const float* arow = XsT + (kc * 32 + kk) * LDX + ty * 4;
                float a0 = arow[0], a1 = arow[1], a2 = arow[2], a3 = arow[3];
                const float* wrow = Wt + kk * Cc + tx * 12;
                float4 b0 = *(const float4*)(wrow);
                float4 b1 = *(const float4*)(wrow + 4);
                float4 b2 = *(const float4*)(wrow + 8);
                float bb[12] = {b0.x,b0.y,b0.z,b0.w, b1.x,b1.y,b1.z,b1.w, b2.x,b2.y,b2.z,b2.w};
                #pragma unroll
                for (int jj = 0; jj < 12; ++jj) {
                    acc[0][jj] = fmaf(a0, bb[jj], acc[0][jj]);
                    acc[1][jj] = fmaf(a1, bb[jj], acc[1][jj]);
                    acc[2][jj] = fmaf(a2, bb[jj], acc[2][jj]);
                    acc[3][jj] = fmaf(a3, bb[jj], acc[3][jj]);
                }
            }
        }
        // epilogue: bias + store to Qt / Kt (transposed) or Vs (token-major)
        #pragma unroll
        for (int jj = 0; jj < 12; ++jj) {
            int j = tx * 12 + jj;
            float bias = qkv_b[p * 192 + j];
            #pragma unroll
            for (int i = 0; i < 4; ++i) {
                float v = acc[i][jj] + bias;
                int r = ty * 4 + i;
                if (p == 0)      Qt[j * LDQ + r] = v;
                else if (p == 1) Kt[j * LDQ + r] = v;
                else             Vs[r * Cc + j] = v;
            }
        }
    }
    __syncthreads();

    // ---- Attention per head ----
    const float scale = 0.17677669529663687f;  // 1/sqrt(32)
    float* OsT = XsT;  // reuse (X dead): [192][LDX], col token
    #pragma unroll 1
    for (int h = 0; h < NHh; ++h) {
        // S = scale * Qh @ Kh^T : thread tile 4(q) x 4(k)
        float sacc[4][4];
        #pragma unroll
        for (int i = 0; i < 4; ++i)
            #pragma unroll
            for (int j = 0; j < 4; ++j) sacc[i][j] = 0.0f;

        const float* Qh = Qt + h * 32 * LDQ;
        const float* Kh = Kt + h * 32 * LDQ;
        #pragma unroll 4
        for (int d = 0; d < 32; ++d) {
            const float* qrow = Qh + d * LDQ + ty * 4;
            const float* krow = Kh + d * LDQ + tx * 4;
            float q0 = qrow[0], q1 = qrow[1], q2 = qrow[2], q3 = qrow[3];
            float k0 = krow[0], k1 = krow[1], k2 = krow[2], k3 = krow[3];
            sacc[0][0] = fmaf(q0,k0,sacc[0][0]); sacc[0][1] = fmaf(q0,k1,sacc[0][1]);
            sacc[0][2] = fmaf(q0,k2,sacc[0][2]); sacc[0][3] = fmaf(q0,k3,sacc[0][3]);
            sacc[1][0] = fmaf(q1,k0,sacc[1][0]); sacc[1][1] = fmaf(q1,k1,sacc[1][1]);
            sacc[1][2] = fmaf(q1,k2,sacc[1][2]); sacc[1][3] = fmaf(q1,k3,sacc[1][3]);
            sacc[2][0] = fmaf(q2,k0,sacc[2][0]); sacc[2][1] = fmaf(q2,k1,sacc[2][1]);
            sacc[2][2] = fmaf(q2,k2,sacc[2][2]); sacc[2][3] = fmaf(q2,k3,sacc[2][3]);
            sacc[3][0] = fmaf(q3,k0,sacc[3][0]); sacc[3][1] = fmaf(q3,k1,sacc[3][1]);
            sacc[3][2] = fmaf(q3,k2,sacc[3][2]); sacc[3][3] = fmaf(q3,k3,sacc[3][3]);
        }
        #pragma unroll
        for (int i = 0; i < 4; ++i)
            #pragma unroll
            for (int j = 0; j < 4; ++j)
                S[(ty * 4 + i) * 64 + tx * 4 + j] = sacc[i][j] * scale;
        __syncthreads();

        // softmax: each warp owns 8 rows, 2 values per lane
        {
            int warp = tid >> 5, lane = tid & 31;
            #pragma unroll 1
            for (int rr = 0; rr < 8; ++rr) {
                int row = warp * 8 + rr;
                float v0 = S[row * 64 + lane];
                float v1 = S[row * 64 + 32 + lane];
                float m = fmaxf(v0, v1);
                #pragma unroll
                for (int off = 16; off > 0; off >>= 1)
                    m = fmaxf(m, __shfl_xor_sync(0xFFFFFFFFu, m, off));
                float e0 = __expf(v0 - m);
                float e1 = __expf(v1 - m);
                float s = e0 + e1;
                #pragma unroll
                for (int off = 16; off > 0; off >>= 1)
                    s += __shfl_xor_sync(0xFFFFFFFFu, s, off);
                float inv = __frcp_rn(s);
                S[row * 64 + lane]      = e0 * inv;
                S[row * 64 + 32 + lane] = e1 * inv;
            }
        }
        __syncthreads();

        // O = P @ Vh : thread tile 4(q) x 2(d)
        float oacc[4][2] = {{0,0},{0,0},{0,0},{0,0}};
        const float* Vh = Vs + h * 32 + tx * 2;
        #pragma unroll 8
        for (int k = 0; k < 64; ++k) {
            float v0 = Vh[k * Cc];
            float v1 = Vh[k * Cc + 1];
            const float* prow = S + ty * 4 * 64 + k;
            float p0 = prow[0], p1 = prow[64], p2 = prow[128], p3 = prow[192];
            oacc[0][0] = fmaf(p0, v0, oacc[0][0]); oacc[0][1] = fmaf(p0, v1, oacc[0][1]);
            oacc[1][0] = fmaf(p1, v0, oacc[1][0]); oacc[1][1] = fmaf(p1, v1, oacc[1][1]);
            oacc[2][0] = fmaf(p2, v0, oacc[2][0]); oacc[2][1] = fmaf(p2, v1, oacc[2][1]);
            oacc[3][0] = fmaf(p3, v0, oacc[3][0]); oacc[3][1] = fmaf(p3, v1, oacc[3][1]);
        }
        #pragma unroll
        for (int i = 0; i < 4; ++i) {
            OsT[(h * 32 + tx * 2)     * LDX + ty * 4 + i] = oacc[i][0];
            OsT[(h * 32 + tx * 2 + 1) * LDX + ty * 4 + i] = oacc[i][1];
        }
        __syncthreads();  // S reused next head
    }

    // ---- Proj GEMM: OsT (A^T) @ proj_w -> Res [c][t] (Qt region) ----
    {
        float pacc[4][12];
        #pragma unroll
        for (int i = 0; i < 4; ++i)
            #pragma unroll
            for (int jj = 0; jj < 12; ++jj) pacc[i][jj] = 0.0f;

        #pragma unroll 1
        for (int kc = 0; kc < 6; ++kc) {
            __syncthreads();
            // proj_w rows kc*32..+31 are 6144 contiguous floats
            for (int v = tid; v < (32 * Cc) / 4; v += 256)
                ((float4*)Wt)[v] = ((const float4*)(proj_w + kc * 6144))[v];
            __syncthreads();

            #pragma unroll 4
            for (int kk = 0; kk < 32; ++kk) {
                const float* arow = OsT + (kc * 32 + kk) * LDX + ty * 4;
                float a0 = arow[0], a1 = arow[1], a2 = arow[2], a3 = arow[3];
                const float* wrow = Wt + kk * Cc + tx * 12;
                float4 b0 = *(const float4*)(wrow);
                float4 b1 = *(const float4*)(wrow + 4);
                float4 b2 = *(const float4*)(wrow + 8);
                float bb[12] = {b0.x,b0.y,b0.z,b0.w, b1.x,b1.y,b1.z,b1.w, b2.x,b2.y,b2.z,b2.w};
                #pragma unroll
                for (int jj = 0; jj < 12; ++jj) {
                    pacc[0][jj] = fmaf(a0, bb[jj], pacc[0][jj]);
                    pacc[1][jj] = fmaf(a1, bb[jj], pacc[1][jj]);
                    pacc[2][jj] = fmaf(a2, bb[jj], pacc[2][jj]);
                    pacc[3][jj] = fmaf(a3, bb[jj], pacc[3][jj]);
                }
            }
        }
        float* Res = Qt;  // reuse: [192][LDX] channel-major
        #pragma unroll
        for (int jj = 0; jj < 12; ++jj) {
            int j = tx * 12 + jj;
            float bias = proj_b[j];
            #pragma unroll
            for (int i = 0; i < 4; ++i)
                Res[j * LDX + ty * 4 + i] = pacc[i][jj] + bias;
        }
    }
    __syncthreads();

    // ---- Scatter back to NCHW with reverse roll (same index map) ----
    {
        const float* Res = Qt;
        float* ob = out + (size_t)b * Cc * 65536;
        for (int idx = tid; idx < Cc * Tt; idx += 256) {
            int c = idx >> 6, t = idx & 63;
            int oh = (baseH + (t >> 3)) & 255;
            int ow = (baseW + (t & 7)) & 255;
            ob[c * 65536 + oh * 256 + ow] = Res[c * LDX + t];
        }
    }
}

extern "C" void kernel_launch(void* const* d_in, const int* in_sizes, int n_in,
                              void* d_out, int out_size)
{
    const float* x      = (const float*)d_in[0];
    const float* qkv_w  = (const float*)d_in[1];
    const float* qkv_b  = (const float*)d_in[2];
    const float* proj_w = (const float*)d_in[3];
    const float* proj_b = (const float*)d_in[4];
    float* out = (float*)d_out;

    cudaFuncSetAttribute(swin_fused_kernel,
                         cudaFuncAttributeMaxDynamicSharedMemorySize, SMEM_BYTES);
    swin_fused_kernel<<<NWIN, 256, SMEM_BYTES>>>(x, qkv_w, qkv_b, proj_w, proj_b, out);
}

// round 5
// speedup vs baseline: 2.3643x; 2.3643x over previous
#include <cuda_runtime.h>
#include <cstdint>

// Problem constants
#define Cc    192
#define Tt    64
#define NWIN  4096
#define SHIFTc 4

// SMEM strides (floats) — chosen so (stride mod 32) spreads banks:
//  LDA=196 -> 4*row+col distinct over a warp's fragment loads
//  LDW/LDV=200 -> 8*k+col distinct
//  LDSS=68 -> 4*row+col distinct
#define LDA   196
#define LDV   200
#define LDW   200
#define LDSS  68
#define LDRES 65

// SMEM layout (floats)
#define OFF_X 0        // Xs [64][196] = 12544 ; reused as Os
#define OFF_Q 12544    // Qs [64][196]         ; reused as Res [192][65]
#define OFF_K 25088    // Ks [64][196]
#define OFF_V 37632    // Vs [64][200] = 12800
#define OFF_W 50432    // Wt [32][200] = 6400  ; reused as S [64][68] = 4352
#define SMEM_FLOATS 56832
#define SMEM_BYTES  (SMEM_FLOATS * 4)   // 227328

__device__ __forceinline__ float to_tf32(float f) {
    uint32_t u;
    asm("cvt.rna.tf32.f32 %0, %1;" : "=r"(u) : "f"(f));
    return __uint_as_float(u);
}

__device__ __forceinline__ void mma8(float* c, const uint32_t* a, const uint32_t* b) {
    asm volatile(
        "mma.sync.aligned.m16n8k8.row.col.f32.tf32.tf32.f32 "
        "{%0,%1,%2,%3}, {%4,%5,%6,%7}, {%8,%9}, {%0,%1,%2,%3};"
        : "+f"(c[0]), "+f"(c[1]), "+f"(c[2]), "+f"(c[3])
        : "r"(a[0]), "r"(a[1]), "r"(a[2]), "r"(a[3]),
          "r"(b[0]), "r"(b[1]));
}

__global__ void __launch_bounds__(256, 1)
swin_tf32_kernel(const float* __restrict__ x,
                 const float* __restrict__ qkv_w,
                 const float* __restrict__ qkv_b,
                 const float* __restrict__ proj_w,
                 const float* __restrict__ proj_b,
                 float* __restrict__ out)
{
    extern __shared__ float smem[];
    float* Xs = smem + OFF_X;   // token-major [t][c], tf32; later Os
    float* Qs = smem + OFF_Q;   // token-major [t][c], tf32; later Res [c][t]
    float* Ks = smem + OFF_K;   // token-major
    float* Vs = smem + OFF_V;   // token-major
    float* Wt = smem + OFF_W;   // [32][200] weight chunk, tf32; also S [64][68]
    float* S  = Wt;

    const int tid  = threadIdx.x;
    const int warp = tid >> 5;
    const int lane = tid & 31;
    const int grp  = lane >> 2;   // 0..7
    const int tig  = lane & 3;    // 0..3
    const int warp_m = warp >> 2; // 0..1  (32 rows each)
    const int warp_n = warp & 3;  // 0..3

    const int wid = blockIdx.x;
    const int b  = wid >> 10;
    const int wy = (wid >> 5) & 31;
    const int wx = wid & 31;
    const int baseH = wy * 8 + SHIFTc;
    const int baseW = wx * 8 + SHIFTc;

    // ---- Gather window input with roll -> Xs[t][c] (tf32), coalesced GMEM ----
    {
        const float* xb = x + (size_t)b * Cc * 65536;
        for (int idx = tid; idx < Cc * Tt; idx += 256) {
            int c = idx >> 6, t = idx & 63;
            int ih = (baseH + (t >> 3)) & 255;
            int iw = (baseW + (t & 7)) & 255;
            Xs[t * LDA + c] = to_tf32(xb[c * 65536 + ih * 256 + iw]);
        }
    }

    // ---- QKV GEMM: 3 passes, each 64x192 = Xs @ Wp, K=192 ----
    #pragma unroll 1
    for (int p = 0; p < 3; ++p) {
        float acc[2][6][4];
        #pragma unroll
        for (int mt = 0; mt < 2; ++mt)
            #pragma unroll
            for (int nt = 0; nt < 6; ++nt)
                #pragma unroll
                for (int i = 0; i < 4; ++i) acc[mt][nt][i] = 0.0f;

        #pragma unroll 1
        for (int kc = 0; kc < 6; ++kc) {
            __syncthreads();
            // stage weight chunk rows kc*32..+31, cols p*192..+191 (tf32)
            for (int v4 = tid; v4 < 32 * 48; v4 += 256) {
                int row = v4 / 48, c4 = (v4 % 48) * 4;
                float4 w = *(const float4*)(qkv_w + (size_t)(kc * 32 + row) * 576 + p * 192 + c4);
                w.x = to_tf32(w.x); w.y = to_tf32(w.y);
                w.z = to_tf32(w.z); w.w = to_tf32(w.w);
                *(float4*)(Wt + row * LDW + c4) = w;
            }
            __syncthreads();

            #pragma unroll
            for (int ks = 0; ks < 4; ++ks) {
                const int kb = kc * 32 + ks * 8;
                uint32_t a[2][4];
                #pragma unroll
                for (int mt = 0; mt < 2; ++mt) {
                    const float* ap = Xs + (warp_m * 32 + mt * 16 + grp) * LDA + kb + tig;
                    a[mt][0] = __float_as_uint(ap[0]);
                    a[mt][1] = __float_as_uint(ap[8 * LDA]);
                    a[mt][2] = __float_as_uint(ap[4]);
                    a[mt][3] = __float_as_uint(ap[8 * LDA + 4]);
                }
                uint32_t bb[6][2];
                #pragma unroll
                for (int nt = 0; nt < 6; ++nt) {
                    const float* bp = Wt + (ks * 8 + tig) * LDW + warp_n * 48 + nt * 8 + grp;
                    bb[nt][0] = __float_as_uint(bp[0]);
                    bb[nt][1] = __float_as_uint(bp[4 * LDW]);
                }
                #pragma unroll
                for (int mt = 0; mt < 2; ++mt)
                    #pragma unroll
                    for (int nt = 0; nt < 6; ++nt)
                        mma8(acc[mt][nt], a[mt], bb[nt]);
            }
        }
        // epilogue: bias + tf32-convert + store to Qs/Ks/Vs
        float* dst = (p == 0) ? Qs : (p == 1) ? Ks : Vs;
        const int ld = (p == 2) ? LDV : LDA;
        #pragma unroll
        for (int nt = 0; nt < 6; ++nt) {
            int col = warp_n * 48 + nt * 8 + 2 * tig;
            float bia0 = qkv_b[p * 192 + col];
            float bia1 = qkv_b[p * 192 + col + 1];
            #pragma unroll
            for (int mt = 0; mt < 2; ++mt) {
                int r0 = warp_m * 32 + mt * 16 + grp;
                float2 v0 = make_float2(to_tf32(acc[mt][nt][0] + bia0),
                                        to_tf32(acc[mt][nt][1] + bia1));
                float2 v1 = make_float2(to_tf32(acc[mt][nt][2] + bia0),
                                        to_tf32(acc[mt][nt][3] + bia1));
                *(float2*)(dst + r0 * ld + col)       = v0;
                *(float2*)(dst + (r0 + 8) * ld + col) = v1;
            }
        }
    }
    __syncthreads();

    // ---- Attention per head (tensor-core S and O) ----
    const float scale = 0.17677669529663687f;  // 1/sqrt(32)
    float* Os = Xs;  // X dead
    #pragma unroll 1
    for (int h = 0; h < 6; ++h) {
        // S = scale * Qh @ Kh^T : per warp 2 m-tiles x 2 n-tiles, K=32
        float sacc[2][2][4];
        #pragma unroll
        for (int mt = 0; mt < 2; ++mt)
            #pragma unroll
            for (int nt = 0; nt < 2; ++nt)
                #pragma unroll
                for (int i = 0; i < 4; ++i) sacc[mt][nt][i] = 0.0f;

        #pragma unroll
        for (int ks = 0; ks < 4; ++ks) {
            const int kb = h * 32 + ks * 8;
            uint32_t a[2][4];
            #pragma unroll
            for (int mt = 0; mt < 2; ++mt) {
                const float* ap = Qs + (warp_m * 32 + mt * 16 + grp) * LDA + kb + tig;
                a[mt][0] = __float_as_uint(ap[0]);
                a[mt][1] = __float_as_uint(ap[8 * LDA]);
                a[mt][2] = __float_as_uint(ap[4]);
                a[mt][3] = __float_as_uint(ap[8 * LDA + 4]);
            }
            uint32_t bb[2][2];
            #pragma unroll
            for (int nt = 0; nt < 2; ++nt) {
                const float* bp = Ks + (warp_n * 16 + nt * 8 + grp) * LDA + kb + tig;
                bb[nt][0] = __float_as_uint(bp[0]);
                bb[nt][1] = __float_as_uint(bp[4]);
            }
            #pragma unroll
            for (int mt = 0; mt < 2; ++mt)
                #pragma unroll
                for (int nt = 0; nt < 2; ++nt)
                    mma8(sacc[mt][nt], a[mt], bb[nt]);
        }
        #pragma unroll
        for (int nt = 0; nt < 2; ++nt) {
            int col = warp_n * 16 + nt * 8 + 2 * tig;
            #pragma unroll
            for (int mt = 0; mt < 2; ++mt) {
                int r0 = warp_m * 32 + mt * 16 + grp;
                *(float2*)(S + r0 * LDSS + col) =
                    make_float2(sacc[mt][nt][0] * scale, sacc[mt][nt][1] * scale);
                *(float2*)(S + (r0 + 8) * LDSS + col) =
                    make_float2(sacc[mt][nt][2] * scale, sacc[mt][nt][3] * scale);
            }
        }
        __syncthreads();

        // softmax rows (fp32), store P back as tf32
        #pragma unroll 1
        for (int rr = 0; rr < 8; ++rr) {
            int row = warp * 8 + rr;
            float v0 = S[row * LDSS + lane];
            float v1 = S[row * LDSS + 32 + lane];
            float m = fmaxf(v0, v1);
            #pragma unroll
            for (int off = 16; off > 0; off >>= 1)
                m = fmaxf(m, __shfl_xor_sync(0xFFFFFFFFu, m, off));
            float e0 = __expf(v0 - m);
            float e1 = __expf(v1 - m);
            float s = e0 + e1;
            #pragma unroll
            for (int off = 16; off > 0; off >>= 1)
                s += __shfl_xor_sync(0xFFFFFFFFu, s, off);
            float inv = __frcp_rn(s);
            S[row * LDSS + lane]      = to_tf32(e0 * inv);
            S[row * LDSS + 32 + lane] = to_tf32(e1 * inv);
        }
        __syncthreads();

        // O = P @ Vh : per warp 2 m-tiles x 1 n-tile (8 of 32 d-cols), K=64
        float oacc[2][4];
        #pragma unroll
        for (int mt = 0; mt < 2; ++mt)
            #pragma unroll
            for (int i = 0; i < 4; ++i) oacc[mt][i] = 0.0f;

        #pragma unroll
        for (int ks = 0; ks < 8; ++ks) {
            uint32_t a[2][4];
            #pragma unroll
            for (int mt = 0; mt < 2; ++mt) {
                const float* ap = S + (warp_m * 32 + mt * 16 + grp) * LDSS + ks * 8 + tig;
                a[mt][0] = __float_as_uint(ap[0]);
                a[mt][1] = __float_as_uint(ap[8 * LDSS]);
                a[mt][2] = __float_as_uint(ap[4]);
                a[mt][3] = __float_as_uint(ap[8 * LDSS + 4]);
            }
            uint32_t bb[2];
            const float* bp = Vs + (ks * 8 + tig) * LDV + h * 32 + warp_n * 8 + grp;
            bb[0] = __float_as_uint(bp[0]);
            bb[1] = __float_as_uint(bp[4 * LDV]);
            mma8(oacc[0], a[0], bb);
            mma8(oacc[1], a[1], bb);
        }
        {
            int col = h * 32 + warp_n * 8 + 2 * tig;
            #pragma unroll
            for (int mt = 0; mt < 2; ++mt) {
                int r0 = warp_m * 32 + mt * 16 + grp;
                *(float2*)(Os + r0 * LDA + col) =
                    make_float2(to_tf32(oacc[mt][0]), to_tf32(oacc[mt][1]));
                *(float2*)(Os + (r0 + 8) * LDA + col) =
                    make_float2(to_tf32(oacc[mt][2]), to_tf32(oacc[mt][3]));
            }
        }
        __syncthreads();  // S reused next head; Os visible for proj
    }

    // ---- Proj GEMM: Res[c][t] = (Os @ proj_w + b)^T ----
    {
        float pacc[2][6][4];
        #pragma unroll
        for (int mt = 0; mt < 2; ++mt)
            #pragma unroll
            for (int nt = 0; nt < 6; ++nt)
                #pragma unroll
                for (int i = 0; i < 4; ++i) pacc[mt][nt][i] = 0.0f;

        #pragma unroll 1
        for (int kc = 0; kc < 6; ++kc) {
            __syncthreads();
            for (int v4 = tid; v4 < 32 * 48; v4 += 256) {
                float4 w = ((const float4*)(proj_w + kc * 6144))[v4];
                w.x = to_tf32(w.x); w.y = to_tf32(w.y);
                w.z = to_tf32(w.z); w.w = to_tf32(w.w);
                int row = v4 / 48, c4 = (v4 % 48) * 4;
                *(float4*)(Wt + row * LDW + c4) = w;
            }
            __syncthreads();

            #pragma unroll
            for (int ks = 0; ks < 4; ++ks) {
                const int kb = kc * 32 + ks * 8;
                uint32_t a[2][4];
                #pragma unroll
                for (int mt = 0; mt < 2; ++mt) {
                    const float* ap = Os + (warp_m * 32 + mt * 16 + grp) * LDA + kb + tig;
                    a[mt][0] = __float_as_uint(ap[0]);
                    a[mt][1] = __float_as_uint(ap[8 * LDA]);
                    a[mt][2] = __float_as_uint(ap[4]);
                    a[mt][3] = __float_as_uint(ap[8 * LDA + 4]);
                }
                uint32_t bb[6][2];
                #pragma unroll
                for (int nt = 0; nt < 6; ++nt) {
                    const float* bp = Wt + (ks * 8 + tig) * LDW + warp_n * 48 + nt * 8 + grp;
                    bb[nt][0] = __float_as_uint(bp[0]);
                    bb[nt][1] = __float_as_uint(bp[4 * LDW]);
                }
                #pragma unroll
                for (int mt = 0; mt < 2; ++mt)
                    #pragma unroll
                    for (int nt = 0; nt < 6; ++nt)
                        mma8(pacc[mt][nt], a[mt], bb[nt]);
            }
        }
        // epilogue: bias, transpose-store channel-major Res (Qs region, fp32)
        float* Res = Qs;
        #pragma unroll
        for (int nt = 0; nt < 6; ++nt) {
            int col = warp_n * 48 + nt * 8 + 2 * tig;
            float bia0 = proj_b[col];
            float bia1 = proj_b[col + 1];
            #pragma unroll
            for (int mt = 0; mt < 2; ++mt) {
                int r0 = warp_m * 32 + mt * 16 + grp;
                Res[col * LDRES + r0]           = pacc[mt][nt][0] + bia0;
                Res[(col + 1) * LDRES + r0]     = pacc[mt][nt][1] + bia1;
                Res[col * LDRES + r0 + 8]       = pacc[mt][nt][2] + bia0;
                Res[(col + 1) * LDRES + r0 + 8] = pacc[mt][nt][3] + bia1;
            }
        }
    }
    __syncthreads();

    // ---- Scatter back to NCHW with reverse roll ----
    {
        const float* Res = Qs;
        float* ob = out + (size_t)b * Cc * 65536;
        for (int idx = tid; idx < Cc * Tt; idx += 256) {
            int c = idx >> 6, t = idx & 63;
            int oh = (baseH + (t >> 3)) & 255;
            int ow = (baseW + (t & 7)) & 255;
            ob[c * 65536 + oh * 256 + ow] = Res[c * LDRES + t];
        }
    }
}

extern "C" void kernel_launch(void* const* d_in, const int* in_sizes, int n_in,
                              void* d_out, int out_size)
{
    const float* x      = (const float*)d_in[0];
    const float* qkv_w  = (const float*)d_in[1];
    const float* qkv_b  = (const float*)d_in[2];
    const float* proj_w = (const float*)d_in[3];
    const float* proj_b = (const float*)d_in[4];
    float* out = (float*)d_out;

    cudaFuncSetAttribute(swin_tf32_kernel,
                         cudaFuncAttributeMaxDynamicSharedMemorySize, SMEM_BYTES);
    swin_tf32_kernel<<<NWIN, 256, SMEM_BYTES>>>(x, qkv_w, qkv_b, proj_w, proj_b, out);
}

// round 7
// speedup vs baseline: 4.3955x; 1.8591x over previous
#include <cuda_runtime.h>
#include <cstdint>

// Problem constants
#define Cc    192
#define Tt    64
#define NWIN  4096
#define SHIFTc 4

// SMEM strides (floats), chosen for conflict-free fragment access:
//  LDA=196 (mod 32 = 4): A-frag banks 4*grp+tig distinct
//  LDW/LDV=200 (mod 32 = 8): B-frag banks 8*tig+grp distinct
//  LDSS=68 (mod 32 = 4)
#define LDA   196
#define LDV   200
#define LDW   200
#define LDSS  68
#define LDRES 65

// SMEM layout (floats)
#define OFF_X 0        // Xs [64][196] = 12544 ; reused as Os
#define OFF_Q 12544    // Qs [64][196]         ; reused as Res [192][65]
#define OFF_K 25088    // Ks [64][196]
#define OFF_V 37632    // Vs [64][200] = 12800
#define OFF_W 50432    // Wt [32][200] = 6400  ; reused as S [64][68] = 4352
#define SMEM_FLOATS 56832
#define SMEM_BYTES  (SMEM_FLOATS * 4)   // 227328

__device__ __forceinline__ float to_tf32(float f) {
    uint32_t u;
    asm("cvt.rna.tf32.f32 %0, %1;" : "=r"(u) : "f"(f));
    return __uint_as_float(u);
}

__device__ __forceinline__ void mma8(float* c, const uint32_t* a, const uint32_t* b) {
    asm volatile(
        "mma.sync.aligned.m16n8k8.row.col.f32.tf32.tf32.f32 "
        "{%0,%1,%2,%3}, {%4,%5,%6,%7}, {%8,%9}, {%0,%1,%2,%3};"
        : "+f"(c[0]), "+f"(c[1]), "+f"(c[2]), "+f"(c[3])
        : "r"(a[0]), "r"(a[1]), "r"(a[2]), "r"(a[3]),
          "r"(b[0]), "r"(b[1]));
}

__global__ void __launch_bounds__(512, 1)
swin_tf32_kernel(const float* __restrict__ x,
                 const float* __restrict__ qkv_w,
                 const float* __restrict__ qkv_b,
                 const float* __restrict__ proj_w,
                 const float* __restrict__ proj_b,
                 float* __restrict__ out)
{
    extern __shared__ float smem[];
    float* Xs = smem + OFF_X;   // token-major [t][c], tf32; later Os
    float* Qs = smem + OFF_Q;   // token-major [t][c], tf32; later Res [c][t]
    float* Ks = smem + OFF_K;
    float* Vs = smem + OFF_V;
    float* Wt = smem + OFF_W;   // [32][200] weight chunk, tf32; also S [64][68]
    float* S  = Wt;

    const int tid  = threadIdx.x;
    const int warp = tid >> 5;     // 0..15
    const int lane = tid & 31;
    const int grp  = lane >> 2;    // 0..7
    const int tig  = lane & 3;     // 0..3
    const int warp_m = warp >> 2;  // 0..3  (16 rows each)
    const int warp_n = warp & 3;   // 0..3

    const int wid = blockIdx.x;
    const int b  = wid >> 10;
    const int wy = (wid >> 5) & 31;
    const int wx = wid & 31;
    const int baseH = wy * 8 + SHIFTc;
    const int baseW = wx * 8 + SHIFTc;

    // staging decomposition for 32x192 weight chunk: 1536 float4, 512 threads -> 3 each
    const int st_row0 = tid / 48;            // rows for j=0 slice (tid 0..511 -> v4 = tid)
    // we compute per-j below instead

    // ---- Gather window input with roll -> Xs[t][c] (tf32) ----
    {
        const float* xb = x + (size_t)b * Cc * 65536;
        #pragma unroll
        for (int it = 0; it < 24; ++it) {
            int idx = tid + it * 512;
            int c = idx >> 6, t = idx & 63;
            int ih = (baseH + (t >> 3)) & 255;
            int iw = (baseW + (t & 7)) & 255;
            Xs[t * LDA + c] = to_tf32(xb[c * 65536 + ih * 256 + iw]);
        }
    }

    // ---- QKV GEMM: 3 passes, each 64x192 = Xs @ Wp, K=192 ----
    #pragma unroll 1
    for (int p = 0; p < 3; ++p) {
        float acc[6][4];
        #pragma unroll
        for (int nt = 0; nt < 6; ++nt)
            #pragma unroll
            for (int i = 0; i < 4; ++i) acc[nt][i] = 0.0f;

        // register prefetch of chunk 0
        float4 wreg[3];
        #pragma unroll
        for (int j = 0; j < 3; ++j) {
            int v4 = tid + j * 512;
            int row = v4 / 48, c4 = (v4 % 48) * 4;
            wreg[j] = *(const float4*)(qkv_w + (size_t)row * 576 + p * 192 + c4);
        }

        #pragma unroll 1
        for (int kc = 0; kc < 6; ++kc) {
            __syncthreads();  // previous chunk consumers done
            #pragma unroll
            for (int j = 0; j < 3; ++j) {
                int v4 = tid + j * 512;
                int row = v4 / 48, c4 = (v4 % 48) * 4;
                float4 w = wreg[j];
                w.x = to_tf32(w.x); w.y = to_tf32(w.y);
                w.z = to_tf32(w.z); w.w = to_tf32(w.w);
                *(float4*)(Wt + row * LDW + c4) = w;
            }
            __syncthreads();
            if (kc < 5) {
                #pragma unroll
                for (int j = 0; j < 3; ++j) {
                    int v4 = tid + j * 512;
                    int row = v4 / 48, c4 = (v4 % 48) * 4;
                    wreg[j] = *(const float4*)(qkv_w + (size_t)(kc * 32 + 32 + row) * 576 + p * 192 + c4);
                }
            }

            #pragma unroll
            for (int ks = 0; ks < 4; ++ks) {
                const int kb = kc * 32 + ks * 8;
                uint32_t a[4];
                const float* ap = Xs + (warp_m * 16 + grp) * LDA + kb + tig;
                a[0] = __float_as_uint(ap[0]);
                a[1] = __float_as_uint(ap[8 * LDA]);
                a[2] = __float_as_uint(ap[4]);
                a[3] = __float_as_uint(ap[8 * LDA + 4]);
                uint32_t bb[6][2];
                #pragma unroll
                for (int nt = 0; nt < 6; ++nt) {
                    const float* bp = Wt + (ks * 8 + tig) * LDW + warp_n * 48 + nt * 8 + grp;
                    bb[nt][0] = __float_as_uint(bp[0]);
                    bb[nt][1] = __float_as_uint(bp[4 * LDW]);
                }
                #pragma unroll
                for (int nt = 0; nt < 6; ++nt)
                    mma8(acc[nt], a, bb[nt]);
            }
        }
        // epilogue: bias + tf32 + store
        float* dst = (p == 0) ? Qs : (p == 1) ? Ks : Vs;
        const int ld = (p == 2) ? LDV : LDA;
        #pragma unroll
        for (int nt = 0; nt < 6; ++nt) {
            int col = warp_n * 48 + nt * 8 + 2 * tig;
            float bia0 = qkv_b[p * 192 + col];
            float bia1 = qkv_b[p * 192 + col + 1];
            int r0 = warp_m * 16 + grp;
            *(float2*)(dst + r0 * ld + col) =
                make_float2(to_tf32(acc[nt][0] + bia0), to_tf32(acc[nt][1] + bia1));
            *(float2*)(dst + (r0 + 8) * ld + col) =
                make_float2(to_tf32(acc[nt][2] + bia0), to_tf32(acc[nt][3] + bia1));
        }
    }
    __syncthreads();

    // ---- Attention per head ----
    const float scale = 0.17677669529663687f;  // 1/sqrt(32)
    float* Os = Xs;  // X dead
    #pragma unroll 1
    for (int h = 0; h < 6; ++h) {
        // S = scale * Qh @ Kh^T : warp tile m16 x n16 (2 n-tiles), K=32
        float sacc[2][4];
        #pragma unroll
        for (int nt = 0; nt < 2; ++nt)
            #pragma unroll
            for (int i = 0; i < 4; ++i) sacc[nt][i] = 0.0f;

        #pragma unroll
        for (int ks = 0; ks < 4; ++ks) {
            const int kb = h * 32 + ks * 8;
            uint32_t a[4];
            const float* ap = Qs + (warp_m * 16 + grp) * LDA + kb + tig;
            a[0] = __float_as_uint(ap[0]);
            a[1] = __float_as_uint(ap[8 * LDA]);
            a[2] = __float_as_uint(ap[4]);
            a[3] = __float_as_uint(ap[8 * LDA + 4]);
            uint32_t bb[2][2];
            #pragma unroll
            for (int nt = 0; nt < 2; ++nt) {
                const float* bp = Ks + (warp_n * 16 + nt * 8 + grp) * LDA + kb + tig;
                bb[nt][0] = __float_as_uint(bp[0]);
                bb[nt][1] = __float_as_uint(bp[4]);
            }
            mma8(sacc[0], a, bb[0]);
            mma8(sacc[1], a, bb[1]);
        }
        #pragma unroll
        for (int nt = 0; nt < 2; ++nt) {
            int col = warp_n * 16 + nt * 8 + 2 * tig;
            int r0 = warp_m * 16 + grp;
            *(float2*)(S + r0 * LDSS + col) =
                make_float2(sacc[nt][0] * scale, sacc[nt][1] * scale);
            *(float2*)(S + (r0 + 8) * LDSS + col) =
                make_float2(sacc[nt][2] * scale, sacc[nt][3] * scale);
        }
        __syncthreads();

        // softmax: 4 rows per warp
        #pragma unroll
        for (int rr = 0; rr < 4; ++rr) {
            int row = warp * 4 + rr;
            float v0 = S[row * LDSS + lane];
            float v1 = S[row * LDSS + 32 + lane];
            float m = fmaxf(v0, v1);
            #pragma unroll
            for (int off = 16; off > 0; off >>= 1)
                m = fmaxf(m, __shfl_xor_sync(0xFFFFFFFFu, m, off));
            float e0 = __expf(v0 - m);
            float e1 = __expf(v1 - m);
            float s = e0 + e1;
            #pragma unroll
            for (int off = 16; off > 0; off >>= 1)
                s += __shfl_xor_sync(0xFFFFFFFFu, s, off);
            float inv = __frcp_rn(s);
            S[row * LDSS + lane]      = to_tf32(e0 * inv);
            S[row * LDSS + 32 + lane] = to_tf32(e1 * inv);
        }
        __syncthreads();

        // O = P @ Vh : warp tile m16 x n8, K=64
        float oacc[4] = {0.0f, 0.0f, 0.0f, 0.0f};
        #pragma unroll
        for (int ks = 0; ks < 8; ++ks) {
            uint32_t a[4];
            const float* ap = S + (warp_m * 16 + grp) * LDSS + ks * 8 + tig;
            a[0] = __float_as_uint(ap[0]);
            a[1] = __float_as_uint(ap[8 * LDSS]);
            a[2] = __float_as_uint(ap[4]);
            a[3] = __float_as_uint(ap[8 * LDSS + 4]);
            uint32_t bb[2];
            const float* bp = Vs + (ks * 8 + tig) * LDV + h * 32 + warp_n * 8 + grp;
            bb[0] = __float_as_uint(bp[0]);
            bb[1] = __float_as_uint(bp[4 * LDV]);
            mma8(oacc, a, bb);
        }
        {
            int col = h * 32 + warp_n * 8 + 2 * tig;
            int r0 = warp_m * 16 + grp;
            *(float2*)(Os + r0 * LDA + col) =
                make_float2(to_tf32(oacc[0]), to_tf32(oacc[1]));
            *(float2*)(Os + (r0 + 8) * LDA + col) =
                make_float2(to_tf32(oacc[2]), to_tf32(oacc[3]));
        }
        __syncthreads();  // S reused next head
    }

    // ---- Proj GEMM: Res[c][t] = (Os @ proj_w + b)^T ----
    {
        float pacc[6][4];
        #pragma unroll
        for (int nt = 0; nt < 6; ++nt)
            #pragma unroll
            for (int i = 0; i < 4; ++i) pacc[nt][i] = 0.0f;

        float4 wreg[3];
        #pragma unroll
        for (int j = 0; j < 3; ++j)
            wreg[j] = ((const float4*)proj_w)[tid + j * 512];

        #pragma unroll 1
        for (int kc = 0; kc < 6; ++kc) {
            __syncthreads();
            #pragma unroll
            for (int j = 0; j < 3; ++j) {
                int v4 = tid + j * 512;
                int row = v4 / 48, c4 = (v4 % 48) * 4;
                float4 w = wreg[j];
                w.x = to_tf32(w.x); w.y = to_tf32(w.y);
                w.z = to_tf32(w.z); w.w = to_tf32(w.w);
                *(float4*)(Wt + row * LDW + c4) = w;
            }
            __syncthreads();
            if (kc < 5) {
                #pragma unroll
                for (int j = 0; j < 3; ++j)
                    wreg[j] = ((const float4*)(proj_w + (kc + 1) * 6144))[tid + j * 512];
            }

            #pragma unroll
            for (int ks = 0; ks < 4; ++ks) {
                const int kb = kc * 32 + ks * 8;
                uint32_t a[4];
                const float* ap = Os + (warp_m * 16 + grp) * LDA + kb + tig;
                a[0] = __float_as_uint(ap[0]);
                a[1] = __float_as_uint(ap[8 * LDA]);
                a[2] = __float_as_uint(ap[4]);
                a[3] = __float_as_uint(ap[8 * LDA + 4]);
                uint32_t bb[6][2];
                #pragma unroll
                for (int nt = 0; nt < 6; ++nt) {
                    const float* bp = Wt + (ks * 8 + tig) * LDW + warp_n * 48 + nt * 8 + grp;
                    bb[nt][0] = __float_as_uint(bp[0]);
                    bb[nt][1] = __float_as_uint(bp[4 * LDW]);
                }
                #pragma unroll
                for (int nt = 0; nt < 6; ++nt)
                    mma8(pacc[nt], a, bb[nt]);
            }
        }
        // epilogue: bias, transpose-store channel-major Res (fp32)
        float* Res = Qs;
        #pragma unroll
        for (int nt = 0; nt < 6; ++nt) {
            int col = warp_n * 48 + nt * 8 + 2 * tig;
            float bia0 = proj_b[col];
            float bia1 = proj_b[col + 1];
            int r0 = warp_m * 16 + grp;
            Res[col * LDRES + r0]           = pacc[nt][0] + bia0;
            Res[(col + 1) * LDRES + r0]     = pacc[nt][1] + bia1;
            Res[col * LDRES + r0 + 8]       = pacc[nt][2] + bia0;
            Res[(col + 1) * LDRES + r0 + 8] = pacc[nt][3] + bia1;
        }
    }
    __syncthreads();

    // ---- Scatter back to NCHW with reverse roll ----
    {
        const float* Res = Qs;
        float* ob = out + (size_t)b * Cc * 65536;
        #pragma unroll
        for (int it = 0; it < 24; ++it) {
            int idx = tid + it * 512;
            int c = idx >> 6, t = idx & 63;
            int oh = (baseH + (t >> 3)) & 255;
            int ow = (baseW + (t & 7)) & 255;
            ob[c * 65536 + oh * 256 + ow] = Res[c * LDRES + t];
        }
    }
}

extern "C" void kernel_launch(void* const* d_in, const int* in_sizes, int n_in,
                              void* d_out, int out_size)
{
    const float* x      = (const float*)d_in[0];
    const float* qkv_w  = (const float*)d_in[1];
    const float* qkv_b  = (const float*)d_in[2];
    const float* proj_w = (const float*)d_in[3];
    const float* proj_b = (const float*)d_in[4];
    float* out = (float*)d_out;

    cudaFuncSetAttribute(swin_tf32_kernel,
                         cudaFuncAttributeMaxDynamicSharedMemorySize, SMEM_BYTES);
    swin_tf32_kernel<<<NWIN, 512, SMEM_BYTES>>>(x, qkv_w, qkv_b, proj_w, proj_b, out);
}

// round 9
// speedup vs baseline: 5.0860x; 1.1571x over previous
#include <cuda_runtime.h>
#include <cstdint>

// Problem constants
#define Cc 192
#define SHIFTc 4

// ---- gmem scratch (static __device__, per pitfalls.md) ----
__device__ float g_qkv[(size_t)4096 * 3 * 64 * 192];  // [win][p][t][c]
__device__ float g_o[(size_t)4096 * 64 * 192];        // [win][t][c]

__device__ __forceinline__ float to_tf32(float f) {
    uint32_t u;
    asm("cvt.rna.tf32.f32 %0, %1;" : "=r"(u) : "f"(f));
    return __uint_as_float(u);
}

__device__ __forceinline__ void mma8(float* c, const uint32_t* a, const uint32_t* b) {
    asm volatile(
        "mma.sync.aligned.m16n8k8.row.col.f32.tf32.tf32.f32 "
        "{%0,%1,%2,%3}, {%4,%5,%6,%7}, {%8,%9}, {%0,%1,%2,%3};"
        : "+f"(c[0]), "+f"(c[1]), "+f"(c[2]), "+f"(c[3])
        : "r"(a[0]), "r"(a[1]), "r"(a[2]), "r"(a[3]),
          "r"(b[0]), "r"(b[1]));
}

// =====================================================================
// Kernel A: QKV GEMM per window.  smem: Xs[64][196] + Wt[32][200]
// =====================================================================
#define A_SMEM_FLOATS (12544 + 6400)
#define A_SMEM_BYTES  (A_SMEM_FLOATS * 4)   // 75776

__global__ void __launch_bounds__(256, 2)
k_qkv(const float* __restrict__ x,
      const float* __restrict__ qkv_w,
      const float* __restrict__ qkv_b)
{
    extern __shared__ float smem[];
    float* Xs = smem;            // [64][196] tf32
    float* Wt = smem + 12544;    // [32][200] tf32

    const int tid  = threadIdx.x;
    const int warp = tid >> 5, lane = tid & 31;
    const int grp  = lane >> 2, tig = lane & 3;
    const int warp_m = warp >> 2;   // 0..1 (32 rows)
    const int warp_n = warp & 3;    // 0..3 (48 cols)

    const int win = blockIdx.x;
    const int b = win >> 10, wy = (win >> 5) & 31, wx = win & 31;
    const int baseH = wy * 8 + SHIFTc, baseW = wx * 8 + SHIFTc;

    // gather window with roll -> Xs[t][c] (tf32)
    {
        const float* xb = x + (size_t)b * Cc * 65536;
        #pragma unroll
        for (int it = 0; it < 48; ++it) {
            int idx = tid + it * 256;
            int c = idx >> 6, t = idx & 63;
            int ih = (baseH + (t >> 3)) & 255;
            int iw = (baseW + (t & 7)) & 255;
            Xs[t * 196 + c] = to_tf32(xb[c * 65536 + ih * 256 + iw]);
        }
    }

    float* qout = g_qkv + (size_t)win * 36864;

    #pragma unroll 1
    for (int p = 0; p < 3; ++p) {
        float acc[2][6][4];
        #pragma unroll
        for (int mt = 0; mt < 2; ++mt)
            #pragma unroll
            for (int nt = 0; nt < 6; ++nt)
                #pragma unroll
                for (int i = 0; i < 4; ++i) acc[mt][nt][i] = 0.0f;

        float4 wreg[6];
        #pragma unroll
        for (int j = 0; j < 6; ++j) {
            int v4 = tid + j * 256;
            int row = v4 / 48, c4 = (v4 % 48) * 4;
            wreg[j] = *(const float4*)(qkv_w + (size_t)row * 576 + p * 192 + c4);
        }

        #pragma unroll 1
        for (int kc = 0; kc < 6; ++kc) {
            __syncthreads();
            #pragma unroll
            for (int j = 0; j < 6; ++j) {
                int v4 = tid + j * 256;
                int row = v4 / 48, c4 = (v4 % 48) * 4;
                float4 w = wreg[j];
                w.x = to_tf32(w.x); w.y = to_tf32(w.y);
                w.z = to_tf32(w.z); w.w = to_tf32(w.w);
                *(float4*)(Wt + row * 200 + c4) = w;
            }
            __syncthreads();
            if (kc < 5) {
                #pragma unroll
                for (int j = 0; j < 6; ++j) {
                    int v4 = tid + j * 256;
                    int row = v4 / 48, c4 = (v4 % 48) * 4;
                    wreg[j] = *(const float4*)(qkv_w + (size_t)(kc * 32 + 32 + row) * 576 + p * 192 + c4);
                }
            }
            #pragma unroll
            for (int ks = 0; ks < 4; ++ks) {
                int kb = kc * 32 + ks * 8;
                uint32_t a[2][4];
                #pragma unroll
                for (int mt = 0; mt < 2; ++mt) {
                    const float* ap = Xs + (warp_m * 32 + mt * 16 + grp) * 196 + kb + tig;
                    a[mt][0] = __float_as_uint(ap[0]);
                    a[mt][1] = __float_as_uint(ap[8 * 196]);
                    a[mt][2] = __float_as_uint(ap[4]);
                    a[mt][3] = __float_as_uint(ap[8 * 196 + 4]);
                }
                uint32_t bb[6][2];
                #pragma unroll
                for (int nt = 0; nt < 6; ++nt) {
                    const float* bp = Wt + (ks * 8 + tig) * 200 + warp_n * 48 + nt * 8 + grp;
                    bb[nt][0] = __float_as_uint(bp[0]);
                    bb[nt][1] = __float_as_uint(bp[4 * 200]);
                }
                #pragma unroll
                for (int mt = 0; mt < 2; ++mt)
                    #pragma unroll
                    for (int nt = 0; nt < 6; ++nt)
                        mma8(acc[mt][nt], a[mt], bb[nt]);
            }
        }
        // epilogue -> g_qkv[win][p][t][c], tf32 values, coalesced 32B sectors
        float* dst = qout + p * 12288;
        #pragma unroll
        for (int nt = 0; nt < 6; ++nt) {
            int col = warp_n * 48 + nt * 8 + 2 * tig;
            float b0 = qkv_b[p * 192 + col];
            float b1 = qkv_b[p * 192 + col + 1];
            #pragma unroll
            for (int mt = 0; mt < 2; ++mt) {
                int r0 = warp_m * 32 + mt * 16 + grp;
                *(float2*)(dst + r0 * 192 + col) =
                    make_float2(to_tf32(acc[mt][nt][0] + b0), to_tf32(acc[mt][nt][1] + b1));
                *(float2*)(dst + (r0 + 8) * 192 + col) =
                    make_float2(to_tf32(acc[mt][nt][2] + b0), to_tf32(acc[mt][nt][3] + b1));
            }
        }
    }
}

// =====================================================================
// Kernel B: attention per (window, head). 128 threads, 1 barrier total.
// smem: Qh[64][36] Kh[64][36] Vh[64][40] S[64][68]
// =====================================================================
#define LDH  36
#define LDVH 40
#define LDS2 68
#define B_SMEM_FLOATS (2304 + 2304 + 2560 + 4352)
#define B_SMEM_BYTES  (B_SMEM_FLOATS * 4)   // 46080

__global__ void __launch_bounds__(128, 4)
k_attn()
{
    extern __shared__ float smem[];
    float* Qh = smem;
    float* Kh = smem + 2304;
    float* Vh = smem + 4608;
    float* S  = smem + 7168;

    const int tid  = threadIdx.x;
    const int warp = tid >> 5, lane = tid & 31;
    const int grp  = lane >> 2, tig = lane & 3;
    const int win = blockIdx.x, h = blockIdx.y;

    // stage Q,K,V head slices (rows are 128B contiguous in gmem)
    {
        const float* src = g_qkv + (size_t)win * 36864 + h * 32;
        int r = tid >> 3, f4 = (tid & 7) * 4;
        #pragma unroll
        for (int it = 0; it < 4; ++it) {
            int t = r + it * 16;
            float4 q = *(const float4*)(src + t * 192 + f4);
            float4 k = *(const float4*)(src + 12288 + t * 192 + f4);
            float4 v = *(const float4*)(src + 24576 + t * 192 + f4);
            *(float4*)(Qh + t * LDH + f4)  = q;
            *(float4*)(Kh + t * LDH + f4)  = k;
            *(float4*)(Vh + t * LDVH + f4) = v;
        }
    }
    __syncthreads();

    // S = scale * Q @ K^T : warp owns rows warp*16..+15, all 64 cols
    float sacc[8][4];
    #pragma unroll
    for (int nt = 0; nt < 8; ++nt)
        #pragma unroll
        for (int i = 0; i < 4; ++i) sacc[nt][i] = 0.0f;

    #pragma unroll
    for (int ks = 0; ks < 4; ++ks) {
        int kb = ks * 8;
        uint32_t a[4];
        const float* ap = Qh + (warp * 16 + grp) * LDH + kb + tig;
        a[0] = __float_as_uint(ap[0]);
        a[1] = __float_as_uint(ap[8 * LDH]);
        a[2] = __float_as_uint(ap[4]);
        a[3] = __float_as_uint(ap[8 * LDH + 4]);
        #pragma unroll
        for (int nt = 0; nt < 8; ++nt) {
            uint32_t bb[2];
            const float* bp = Kh + (nt * 8 + grp) * LDH + kb + tig;
            bb[0] = __float_as_uint(bp[0]);
            bb[1] = __float_as_uint(bp[4]);
            mma8(sacc[nt], a, bb);
        }
    }
    const float scale = 0.17677669529663687f;  // 1/sqrt(32)
    #pragma unroll
    for (int nt = 0; nt < 8; ++nt) {
        int col = nt * 8 + 2 * tig;
        int r0 = warp * 16 + grp;
        *(float2*)(S + r0 * LDS2 + col) =
            make_float2(sacc[nt][0] * scale, sacc[nt][1] * scale);
        *(float2*)(S + (r0 + 8) * LDS2 + col) =
            make_float2(sacc[nt][2] * scale, sacc[nt][3] * scale);
    }
    __syncwarp();  // warp-local rows; cross-lane smem visibility

    // softmax: 16 rows per warp (its own rows)
    #pragma unroll 1
    for (int rr = 0; rr < 16; ++rr) {
        int row = warp * 16 + rr;
        float v0 = S[row * LDS2 + lane];
        float v1 = S[row * LDS2 + 32 + lane];
        float m = fmaxf(v0, v1);
        #pragma unroll
        for (int off = 16; off > 0; off >>= 1)
            m = fmaxf(m, __shfl_xor_sync(0xFFFFFFFFu, m, off));
        float e0 = __expf(v0 - m);
        float e1 = __expf(v1 - m);
        float s = e0 + e1;
        #pragma unroll
        for (int off = 16; off > 0; off >>= 1)
            s += __shfl_xor_sync(0xFFFFFFFFu, s, off);
        float inv = __frcp_rn(s);
        S[row * LDS2 + lane]      = to_tf32(e0 * inv);
        S[row * LDS2 + 32 + lane] = to_tf32(e1 * inv);
    }
    __syncwarp();

    // O = P @ V : m16 x n32 per warp, K=64
    float oacc[4][4];
    #pragma unroll
    for (int nt = 0; nt < 4; ++nt)
        #pragma unroll
        for (int i = 0; i < 4; ++i) oacc[nt][i] = 0.0f;

    #pragma unroll
    for (int ks = 0; ks < 8; ++ks) {
        uint32_t a[4];
        const float* ap = S + (warp * 16 + grp) * LDS2 + ks * 8 + tig;
        a[0] = __float_as_uint(ap[0]);
        a[1] = __float_as_uint(ap[8 * LDS2]);
        a[2] = __float_as_uint(ap[4]);
        a[3] = __float_as_uint(ap[8 * LDS2 + 4]);
        #pragma unroll
        for (int nt = 0; nt < 4; ++nt) {
            uint32_t bb[2];
            const float* bp = Vh + (ks * 8 + tig) * LDVH + nt * 8 + grp;
            bb[0] = __float_as_uint(bp[0]);
            bb[1] = __float_as_uint(bp[4 * LDVH]);
            mma8(oacc[nt], a, bb);
        }
    }
    // -> g_o[win][t][h*32+d] (tf32 values), coalesced 32B sectors
    float* dst = g_o + (size_t)win * 12288 + h * 32;
    #pragma unroll
    for (int nt = 0; nt < 4; ++nt) {
        int col = nt * 8 + 2 * tig;
        int r0 = warp * 16 + grp;
        *(float2*)(dst + r0 * 192 + col) =
            make_float2(to_tf32(oacc[nt][0]), to_tf32(oacc[nt][1]));
        *(float2*)(dst + (r0 + 8) * 192 + col) =
            make_float2(to_tf32(oacc[nt][2]), to_tf32(oacc[nt][3]));
    }
}

// =====================================================================
// Kernel C: proj GEMM per window + roll-scatter from registers.
// smem: Os[64][196] + Wt[32][200]
// =====================================================================
__global__ void __launch_bounds__(256, 2)
k_proj(const float* __restrict__ proj_w,
       const float* __restrict__ proj_b,
       float* __restrict__ out)
{
    extern __shared__ float smem[];
    float* Os = smem;            // [64][196]
    float* Wt = smem + 12544;    // [32][200]

    const int tid  = threadIdx.x;
    const int warp = tid >> 5, lane = tid & 31;
    const int grp  = lane >> 2, tig = lane & 3;
    const int warp_m = warp >> 2;   // 0..1
    const int warp_n = warp & 3;    // 0..3

    const int win = blockIdx.x;
    const int b = win >> 10, wy = (win >> 5) & 31, wx = win & 31;
    const int baseH = wy * 8 + SHIFTc, baseW = wx * 8 + SHIFTc;

    // stage O tile (values already tf32)
    {
        const float4* og4 = (const float4*)(g_o + (size_t)win * 12288);
        #pragma unroll
        for (int j = 0; j < 12; ++j) {
            int v4 = tid + j * 256;
            int t = v4 / 48, c4 = (v4 % 48) * 4;
            *(float4*)(Os + t * 196 + c4) = og4[v4];
        }
    }

    float pacc[2][6][4];
    #pragma unroll
    for (int mt = 0; mt < 2; ++mt)
        #pragma unroll
        for (int nt = 0; nt < 6; ++nt)
            #pragma unroll
            for (int i = 0; i < 4; ++i) pacc[mt][nt][i] = 0.0f;

    float4 wreg[6];
    #pragma unroll
    for (int j = 0; j < 6; ++j)
        wreg[j] = ((const float4*)proj_w)[tid + j * 256];

    #pragma unroll 1
    for (int kc = 0; kc < 6; ++kc) {
        __syncthreads();
        #pragma unroll
        for (int j = 0; j < 6; ++j) {
            int v4 = tid + j * 256;
            int row = v4 / 48, c4 = (v4 % 48) * 4;
            float4 w = wreg[j];
            w.x = to_tf32(w.x); w.y = to_tf32(w.y);
            w.z = to_tf32(w.z); w.w = to_tf32(w.w);
            *(float4*)(Wt + row * 200 + c4) = w;
        }
        __syncthreads();
        if (kc < 5) {
            #pragma unroll
            for (int j = 0; j < 6; ++j)
                wreg[j] = ((const float4*)(proj_w + (kc + 1) * 6144))[tid + j * 256];
        }
        #pragma unroll
        for (int ks = 0; ks < 4; ++ks) {
            int kb = kc * 32 + ks * 8;
            uint32_t a[2][4];
            #pragma unroll
            for (int mt = 0; mt < 2; ++mt) {
                const float* ap = Os + (warp_m * 32 + mt * 16 + grp) * 196 + kb + tig;
                a[mt][0] = __float_as_uint(ap[0]);
                a[mt][1] = __float_as_uint(ap[8 * 196]);
                a[mt][2] = __float_as_uint(ap[4]);
                a[mt][3] = __float_as_uint(ap[8 * 196 + 4]);
            }
            uint32_t bb[6][2];
            #pragma unroll
            for (int nt = 0; nt < 6; ++nt) {
                const float* bp = Wt + (ks * 8 + tig) * 200 + warp_n * 48 + nt * 8 + grp;
                bb[nt][0] = __float_as_uint(bp[0]);
                bb[nt][1] = __float_as_uint(bp[4 * 200]);
            }
            #pragma unroll
            for (int mt = 0; mt < 2; ++mt)
                #pragma unroll
                for (int nt = 0; nt < 6; ++nt)
                    mma8(pacc[mt][nt], a[mt], bb[nt]);
        }
    }

    // epilogue: bias + roll-scatter straight from registers (NCHW)
    float* ob = out + (size_t)b * Cc * 65536;
    const int ow = (baseW + grp) & 255;
    #pragma unroll
    for (int nt = 0; nt < 6; ++nt) {
        int col = warp_n * 48 + nt * 8 + 2 * tig;
        float b0 = proj_b[col];
        float b1 = proj_b[col + 1];
        #pragma unroll
        for (int mt = 0; mt < 2; ++mt) {
            int t0 = warp_m * 32 + mt * 16;
            int oh0 = (baseH + (t0 >> 3)) & 255;
            int oh1 = (baseH + ((t0 + 8) >> 3)) & 255;
            float* o0 = ob + (size_t)col * 65536;
            float* o1 = o0 + 65536;
            o0[oh0 * 256 + ow] = pacc[mt][nt][0] + b0;
            o1[oh0 * 256 + ow] = pacc[mt][nt][1] + b1;
            o0[oh1 * 256 + ow] = pacc[mt][nt][2] + b0;
            o1[oh1 * 256 + ow] = pacc[mt][nt][3] + b1;
        }
    }
}

extern "C" void kernel_launch(void* const* d_in, const int* in_sizes, int n_in,
                              void* d_out, int out_size)
{
    const float* x      = (const float*)d_in[0];
    const float* qkv_w  = (const float*)d_in[1];
    const float* qkv_b  = (const float*)d_in[2];
    const float* proj_w = (const float*)d_in[3];
    const float* proj_b = (const float*)d_in[4];
    float* out = (float*)d_out;

    cudaFuncSetAttribute(k_qkv,  cudaFuncAttributeMaxDynamicSharedMemorySize, A_SMEM_BYTES);
    cudaFuncSetAttribute(k_attn, cudaFuncAttributeMaxDynamicSharedMemorySize, B_SMEM_BYTES);
    cudaFuncSetAttribute(k_proj, cudaFuncAttributeMaxDynamicSharedMemorySize, A_SMEM_BYTES);

    k_qkv<<<4096, 256, A_SMEM_BYTES>>>(x, qkv_w, qkv_b);
    dim3 gb(4096, 6);
    k_attn<<<gb, 128, B_SMEM_BYTES>>>();
    k_proj<<<4096, 256, A_SMEM_BYTES>>>(proj_w, proj_b, out);
}